// round 3
// baseline (speedup 1.0000x reference)
#include <cuda_runtime.h>
#include <cstdint>

// Problem constants
#define Bn   64
#define Tn   2048
#define In   32
#define Hn   256
#define On   32

// Decomposition: 16 clusters x 8 CTAs. Cluster = one batch group (4 batches),
// each CTA owns 32 hidden units (128 gate rows). h exchanged via DSMEM.
#define NB   16
#define NG   8
#define BPG  4
#define UPC  32
#define JPC  128
#define Kn   288     // K = H + I
#define KH   144     // K/2 (per K-split thread)
#define KP   292     // padded row (292 % 32 == 4 -> conflict-free strided .128)
#define NTHR 256

#define FCROWS 32

// Scratch
__device__ float g_hout[(size_t)Bn * Tn * Hn];   // h history for FC

// ---------- helpers ----------
static __device__ __forceinline__ uint32_t smem_u32(const void* p) {
    uint32_t a;
    asm("{ .reg .u64 t; cvta.to.shared.u64 t, %1; cvt.u32.u64 %0, t; }"
        : "=r"(a) : "l"(p));
    return a;
}
static __device__ __forceinline__ uint32_t ctarank() {
    uint32_t r; asm("mov.u32 %0, %%cluster_ctarank;" : "=r"(r)); return r;
}
static __device__ __forceinline__ void st_dsmem_f32(uint32_t laddr, uint32_t rank, float v) {
    asm volatile("{ .reg .b32 ra; mapa.shared::cluster.u32 ra, %0, %1;"
                 "  st.shared::cluster.f32 [ra], %2; }"
                 :: "r"(laddr), "r"(rank), "f"(v) : "memory");
}
#define CLUSTER_ARRIVE() asm volatile("barrier.cluster.arrive.aligned;" ::: "memory")
#define CLUSTER_WAIT()   asm volatile("barrier.cluster.wait.aligned;"   ::: "memory")

static __device__ __forceinline__ unsigned long long fma2(
    unsigned long long a, unsigned long long b, unsigned long long c) {
    unsigned long long d;
    asm("fma.rn.f32x2 %0, %1, %2, %3;" : "=l"(d) : "l"(a), "l"(b), "l"(c));
    return d;
}
static __device__ __forceinline__ float unpack_sum(unsigned long long v) {
    float2 f = *reinterpret_cast<float2*>(&v);
    return f.x + f.y;
}
static __device__ __forceinline__ float sigm(float xv) {
    return 1.0f / (1.0f + __expf(-xv));
}
static __device__ __forceinline__ float tanh_fast(float xv) {
    xv = fminf(fmaxf(xv, -15.0f), 15.0f);
    float e = __expf(2.0f * xv);
    return __fdividef(e - 1.0f, e + 1.0f);
}

// ---------- persistent LSTM kernel ----------
__global__ void __launch_bounds__(NTHR, 1) __cluster_dims__(NG, 1, 1)
lstm_kernel(const float* __restrict__ x,
            const float* __restrict__ W_ih,
            const float* __restrict__ W_hh,
            const float* __restrict__ b_ih,
            const float* __restrict__ b_hh)
{
    extern __shared__ float smem[];
    float* sW    = smem;                          // [JPC][KP]
    float* sVbuf = sW + JPC * KP;                 // [2][BPG][KP]  double-buffered v
    float* sGate = sVbuf + 2 * BPG * KP;          // [4][BPG][UPC]
    float* sC    = sGate + 4 * BPG * UPC;         // [BPG][UPC]
    float* sBias = sC + BPG * UPC;                // [JPC]
    float* sRed  = sBias + JPC;                   // [2][JPC][BPG]  K-split partials

    const int tid   = threadIdx.x;
    const uint32_t rank = ctarank();              // 0..7 within cluster
    const int group = blockIdx.x / NG;
    const int b0    = group * BPG;
    const int u0    = (int)rank * UPC;

    // ---- one-time setup ----
    for (int idx = tid; idx < JPC * Kn; idx += NTHR) {
        int j = idx / Kn;
        int k = idx - j * Kn;
        int gate = j >> 5, u = j & 31;
        int row  = gate * Hn + u0 + u;            // PyTorch gate order i,f,g,o
        sW[j * KP + k] = (k < Hn) ? W_hh[row * Hn + k] : W_ih[row * In + (k - Hn)];
    }
    for (int j = tid; j < JPC; j += NTHR) {
        int gate = j >> 5, u = j & 31;
        int row = gate * Hn + u0 + u;
        sBias[j] = b_ih[row] + b_hh[row];
    }
    for (int idx = tid; idx < 2 * BPG * KP; idx += NTHR) sVbuf[idx] = 0.0f;
    for (int idx = tid; idx < BPG * UPC; idx += NTHR)   sC[idx]   = 0.0f;
    __syncthreads();
    if (tid < BPG * In) {                          // x(t=0) into buf 0
        int bb = tid / In, i = tid % In;
        sVbuf[bb * KP + Hn + i] = x[((size_t)(b0 + bb) * Tn) * In + i];
    }
    __syncthreads();
    CLUSTER_ARRIVE(); CLUSTER_WAIT();              // init complete cluster-wide

    const uint32_t smem_base = smem_u32(smem);
    // GEMM thread mapping: s = K-half, rr = row pair base (rows rr, rr+64)
    const int s  = tid >> 6;                       // 0/1 (tid<128)
    const int rr = tid & 63;

    for (int t = 0; t < Tn; ++t) {
        const float* sVc = sVbuf + (t & 1) * (BPG * KP);
        float* sVn       = sVbuf + ((t + 1) & 1) * (BPG * KP);

        if (tid < JPC) {
            // ---- gate GEMM: 2 rows x 4 batches x K/2, packed f32x2 ----
            const ulonglong2* w0p = (const ulonglong2*)(sW + rr * KP + s * KH);
            const ulonglong2* w1p = (const ulonglong2*)(sW + (rr + 64) * KP + s * KH);
            const ulonglong2* v0p = (const ulonglong2*)(sVc + 0 * KP + s * KH);
            const ulonglong2* v1p = (const ulonglong2*)(sVc + 1 * KP + s * KH);
            const ulonglong2* v2p = (const ulonglong2*)(sVc + 2 * KP + s * KH);
            const ulonglong2* v3p = (const ulonglong2*)(sVc + 3 * KP + s * KH);
            unsigned long long a00 = 0, a01 = 0, a02 = 0, a03 = 0;
            unsigned long long a10 = 0, a11 = 0, a12 = 0, a13 = 0;
#pragma unroll 4
            for (int kk = 0; kk < KH / 4; ++kk) {
                ulonglong2 w0 = w0p[kk], w1 = w1p[kk];
                ulonglong2 p0 = v0p[kk], p1 = v1p[kk], p2 = v2p[kk], p3 = v3p[kk];
                a00 = fma2(w0.x, p0.x, a00); a01 = fma2(w0.x, p1.x, a01);
                a02 = fma2(w0.x, p2.x, a02); a03 = fma2(w0.x, p3.x, a03);
                a10 = fma2(w1.x, p0.x, a10); a11 = fma2(w1.x, p1.x, a11);
                a12 = fma2(w1.x, p2.x, a12); a13 = fma2(w1.x, p3.x, a13);
                a00 = fma2(w0.y, p0.y, a00); a01 = fma2(w0.y, p1.y, a01);
                a02 = fma2(w0.y, p2.y, a02); a03 = fma2(w0.y, p3.y, a03);
                a10 = fma2(w1.y, p0.y, a10); a11 = fma2(w1.y, p1.y, a11);
                a12 = fma2(w1.y, p2.y, a12); a13 = fma2(w1.y, p3.y, a13);
            }
            // partials: sRed[s][row][b]
            float4 r0 = make_float4(unpack_sum(a00), unpack_sum(a01),
                                    unpack_sum(a02), unpack_sum(a03));
            float4 r1 = make_float4(unpack_sum(a10), unpack_sum(a11),
                                    unpack_sum(a12), unpack_sum(a13));
            *(float4*)(sRed + (s * JPC + rr) * BPG)        = r0;
            *(float4*)(sRed + (s * JPC + rr + 64) * BPG)   = r1;
        } else if (t + 1 < Tn && tid < 128 + BPG * In) {
            // ---- x(t+1) prefetch by otherwise-idle threads ----
            int idx = tid - 128;
            int bb = idx >> 5, i = idx & 31;
            sVn[bb * KP + Hn + i] = x[((size_t)(b0 + bb) * Tn + (t + 1)) * In + i];
        }
        __syncthreads();

        // ---- K-split reduce + bias + activation ----
        if (tid < JPC) {
            int row = tid;
            float4 p0 = *(const float4*)(sRed + row * BPG);
            float4 p1 = *(const float4*)(sRed + (JPC + row) * BPG);
            float bj = sBias[row];
            float g0 = p0.x + p1.x + bj;
            float g1 = p0.y + p1.y + bj;
            float g2 = p0.z + p1.z + bj;
            float g3 = p0.w + p1.w + bj;
            int gate = row >> 5, u = row & 31;
            float r0, r1, r2, r3;
            if (gate == 2) {
                r0 = tanh_fast(g0); r1 = tanh_fast(g1);
                r2 = tanh_fast(g2); r3 = tanh_fast(g3);
            } else {
                r0 = sigm(g0); r1 = sigm(g1); r2 = sigm(g2); r3 = sigm(g3);
            }
            sGate[(gate * BPG + 0) * UPC + u] = r0;
            sGate[(gate * BPG + 1) * UPC + u] = r1;
            sGate[(gate * BPG + 2) * UPC + u] = r2;
            sGate[(gate * BPG + 3) * UPC + u] = r3;
        }
        __syncthreads();

        // ---- c/h update + DSMEM publish into all 8 CTAs' next v-buffer ----
        if (tid < BPG * UPC) {
            int bb = tid >> 5, u = tid & 31;
            float iv = sGate[(0 * BPG + bb) * UPC + u];
            float fv = sGate[(1 * BPG + bb) * UPC + u];
            float gv = sGate[(2 * BPG + bb) * UPC + u];
            float ov = sGate[(3 * BPG + bb) * UPC + u];
            float c  = fmaf(fv, sC[bb * UPC + u], iv * gv);
            sC[bb * UPC + u] = c;
            float h  = ov * tanh_fast(c);
            g_hout[((size_t)(b0 + bb) * Tn + t) * Hn + (u0 + u)] = h;
            if (t + 1 < Tn) {
                uint32_t laddr = smem_base +
                    (uint32_t)(((sVn - smem) + bb * KP + (u0 + u)) * 4);
#pragma unroll
                for (uint32_t dst = 0; dst < NG; ++dst)
                    st_dsmem_f32(laddr, dst, h);
            }
        }

        if (t + 1 < Tn) {
            // release own DSMEM stores; acquire everyone's
            CLUSTER_ARRIVE();
            CLUSTER_WAIT();
        }
    }
}

// ---------- pointwise FC ----------
__global__ void __launch_bounds__(256) fc_kernel(
    const float* __restrict__ fc_w,
    const float* __restrict__ fc_b,
    float* __restrict__ out)
{
    extern __shared__ float fsm[];
    float* s_wT = fsm;                 // [Hn][On]
    float* s_h  = fsm + Hn * On;       // [FCROWS][Hn]
    int tid = threadIdx.x;

    for (int idx = tid; idx < On * Hn; idx += 256) {
        int o = idx / Hn, u = idx % Hn;
        s_wT[u * On + o] = fc_w[idx];
    }
    size_t row0 = (size_t)blockIdx.x * FCROWS;
    for (int idx = tid; idx < FCROWS * (Hn / 4); idx += 256) {
        int r = idx / (Hn / 4), k4 = idx % (Hn / 4);
        *(float4*)(s_h + r * Hn + k4 * 4) =
            *(const float4*)(g_hout + (row0 + r) * Hn + k4 * 4);
    }
    __syncthreads();

    int o  = tid & 31;
    int rg = tid >> 5;
    float acc0 = fc_b[o], acc1 = acc0, acc2 = acc0, acc3 = acc0;
    const float* h0 = s_h + (rg * 4 + 0) * Hn;
    const float* h1 = s_h + (rg * 4 + 1) * Hn;
    const float* h2 = s_h + (rg * 4 + 2) * Hn;
    const float* h3 = s_h + (rg * 4 + 3) * Hn;
#pragma unroll 8
    for (int u = 0; u < Hn; ++u) {
        float wv = s_wT[u * On + o];
        acc0 = fmaf(h0[u], wv, acc0);
        acc1 = fmaf(h1[u], wv, acc1);
        acc2 = fmaf(h2[u], wv, acc2);
        acc3 = fmaf(h3[u], wv, acc3);
    }
    size_t obase = (row0 + (size_t)rg * 4) * On + o;
    out[obase]          = acc0;
    out[obase + On]     = acc1;
    out[obase + 2 * On] = acc2;
    out[obase + 3 * On] = acc3;
}

extern "C" void kernel_launch(void* const* d_in, const int* in_sizes, int n_in,
                              void* d_out, int out_size) {
    const float* x    = (const float*)d_in[0];
    const float* W_ih = (const float*)d_in[1];
    const float* W_hh = (const float*)d_in[2];
    const float* b_ih = (const float*)d_in[3];
    const float* b_hh = (const float*)d_in[4];
    const float* fc_w = (const float*)d_in[5];
    const float* fc_b = (const float*)d_in[6];
    float* out = (float*)d_out;

    const int lstm_smem = (JPC * KP + 2 * BPG * KP + 4 * BPG * UPC +
                           BPG * UPC + JPC + 2 * JPC * BPG) * 4;
    const int fc_smem   = (Hn * On + FCROWS * Hn) * 4;
    cudaFuncSetAttribute(lstm_kernel, cudaFuncAttributeMaxDynamicSharedMemorySize, lstm_smem);
    cudaFuncSetAttribute(fc_kernel,   cudaFuncAttributeMaxDynamicSharedMemorySize, fc_smem);

    lstm_kernel<<<NB * NG, NTHR, lstm_smem>>>(x, W_ih, W_hh, b_ih, b_hh);
    fc_kernel<<<(Bn * Tn) / FCROWS, 256, fc_smem>>>(fc_w, fc_b, out);
}